// round 1
// baseline (speedup 1.0000x reference)
#include <cuda_runtime.h>
#include <cstdint>

// Problem constants (fixed by the reference)
#define HW      65536            // 256*256
#define BATCH   8
#define C0      128
#define NPIX    (BATCH * HW)     // 524288
#define THREADS 256
#define PIX_PER_BLOCK (THREADS * 2)
#define NBLOCKS (NPIX / PIX_PER_BLOCK)   // 1024

// Shared-memory weight layout (float2 units, weights duplicated {w,w} for f32x2 FMA)
// Layer i stored as [c][o] (o contiguous) so inner loops read consecutive pairs via float4.
#define OFF1 0        // 64x128 -> 8192
#define OFF2 8192     // 32x64  -> 2048
#define OFF3 10240    // 16x32  -> 512
#define OFF4 10752    // 8x16   -> 128
#define OFF5 10880    // 4x8    -> 32
#define OFF6 10912    // 2x4    -> 8
#define OFF7 10920    // 1x2    -> 2
#define SMEM_F2 10922
#define SMEM_BYTES (SMEM_F2 * 8)

__device__ __forceinline__ float2 ffma2(float2 a, float2 b, float2 c) {
    unsigned long long ra = reinterpret_cast<unsigned long long&>(a);
    unsigned long long rb = reinterpret_cast<unsigned long long&>(b);
    unsigned long long rc = reinterpret_cast<unsigned long long&>(c);
    unsigned long long rd;
    asm("fma.rn.f32x2 %0, %1, %2, %3;" : "=l"(rd) : "l"(ra), "l"(rb), "l"(rc));
    return reinterpret_cast<float2&>(rd);
}

__device__ __forceinline__ float2 leaky2(float2 v) {
    v.x = fmaxf(v.x, 0.01f * v.x);
    v.y = fmaxf(v.y, 0.01f * v.y);
    return v;
}

// Stage weight matrix w[COUT][CIN] (row-major, global) into shared as
// dst[c*COUT + o] = {w[o][c], w[o][c]}  (transposed + duplicated).
__device__ __forceinline__ void stage_w(float2* dst, const float* __restrict__ w,
                                        int cout, int cin, int tid) {
    int n = cout * cin;
    for (int i = tid; i < n; i += THREADS) {
        int o = i / cin;
        int c = i - o * cin;
        float v = w[i];
        dst[c * cout + o] = make_float2(v, v);
    }
}

// Fused dense layer on packed pixel-pairs: out[o] = sum_c in[c] * w[o][c].
// Weights read as float4 (two duplicated pairs per load) to halve LDS count.
template <int CIN, int COUT>
__device__ __forceinline__ void layerf(const float2* __restrict__ sw,
                                       const float2* in, float2* outv) {
#pragma unroll
    for (int o = 0; o < COUT; ++o) outv[o] = make_float2(0.f, 0.f);
#pragma unroll
    for (int c = 0; c < CIN; ++c) {
        float2 xv = in[c];
        const float4* w4 = reinterpret_cast<const float4*>(sw + c * COUT);
#pragma unroll
        for (int o = 0; o < COUT / 2; ++o) {
            float4 wp = w4[o];
            float2 wa = make_float2(wp.x, wp.y);
            float2 wb = make_float2(wp.z, wp.w);
            outv[2 * o]     = ffma2(xv, wa, outv[2 * o]);
            outv[2 * o + 1] = ffma2(xv, wb, outv[2 * o + 1]);
        }
    }
}

__global__ __launch_bounds__(THREADS, 1)
void fused_mlp7_kernel(const float* __restrict__ x,
                       const float* __restrict__ w1, const float* __restrict__ w2,
                       const float* __restrict__ w3, const float* __restrict__ w4,
                       const float* __restrict__ w5, const float* __restrict__ w6,
                       const float* __restrict__ w7,
                       float* __restrict__ out) {
    extern __shared__ float2 sw[];
    const int tid = threadIdx.x;

    stage_w(sw + OFF1, w1, 64, 128, tid);
    stage_w(sw + OFF2, w2, 32, 64, tid);
    stage_w(sw + OFF3, w3, 16, 32, tid);
    stage_w(sw + OFF4, w4, 8, 16, tid);
    stage_w(sw + OFF5, w5, 4, 8, tid);
    stage_w(sw + OFF6, w6, 2, 4, tid);
    stage_w(sw + OFF7, w7, 1, 2, tid);
    __syncthreads();

    // Global pixel pair handled by this thread
    const int g = blockIdx.x * PIX_PER_BLOCK + tid * 2;  // even, block stays in one image
    const int b = g >> 16;          // image index
    const int p = g & (HW - 1);     // pixel within image

    const float* xp = x + (size_t)b * (C0 * HW) + p;

    // ---- Layer 1: 128 -> 64, streamed from global (coalesced float2) ----
    float2 a0[64];
#pragma unroll
    for (int o = 0; o < 64; ++o) a0[o] = make_float2(0.f, 0.f);

#pragma unroll 2
    for (int c = 0; c < 128; ++c) {
        float2 xv = *reinterpret_cast<const float2*>(xp + (size_t)c * HW);
        const float4* w4 = reinterpret_cast<const float4*>(sw + OFF1 + c * 64);
#pragma unroll
        for (int o = 0; o < 32; ++o) {
            float4 wp = w4[o];
            float2 wa = make_float2(wp.x, wp.y);
            float2 wb = make_float2(wp.z, wp.w);
            a0[2 * o]     = ffma2(xv, wa, a0[2 * o]);
            a0[2 * o + 1] = ffma2(xv, wb, a0[2 * o + 1]);
        }
    }
#pragma unroll
    for (int o = 0; o < 64; ++o) a0[o] = leaky2(a0[o]);

    // ---- Layers 2..6 with LeakyReLU ----
    float2 a1[32];
    layerf<64, 32>(sw + OFF2, a0, a1);
#pragma unroll
    for (int o = 0; o < 32; ++o) a1[o] = leaky2(a1[o]);

    float2 a2[16];
    layerf<32, 16>(sw + OFF3, a1, a2);
#pragma unroll
    for (int o = 0; o < 16; ++o) a2[o] = leaky2(a2[o]);

    float2 a3[8];
    layerf<16, 8>(sw + OFF4, a2, a3);
#pragma unroll
    for (int o = 0; o < 8; ++o) a3[o] = leaky2(a3[o]);

    float2 a4[4];
    layerf<8, 4>(sw + OFF5, a3, a4);
#pragma unroll
    for (int o = 0; o < 4; ++o) a4[o] = leaky2(a4[o]);

    float2 a5[2];
    layerf<4, 2>(sw + OFF6, a4, a5);
#pragma unroll
    for (int o = 0; o < 2; ++o) a5[o] = leaky2(a5[o]);

    // ---- Layer 7: 2 -> 1, no activation ----
    float2 r = ffma2(a5[0], sw[OFF7 + 0], make_float2(0.f, 0.f));
    r = ffma2(a5[1], sw[OFF7 + 1], r);

    *reinterpret_cast<float2*>(out + g) = r;
}

extern "C" void kernel_launch(void* const* d_in, const int* in_sizes, int n_in,
                              void* d_out, int out_size) {
    const float* x  = (const float*)d_in[0];
    const float* w1 = (const float*)d_in[1];
    const float* w2 = (const float*)d_in[2];
    const float* w3 = (const float*)d_in[3];
    const float* w4 = (const float*)d_in[4];
    const float* w5 = (const float*)d_in[5];
    const float* w6 = (const float*)d_in[6];
    const float* w7 = (const float*)d_in[7];
    float* out = (float*)d_out;

    cudaFuncSetAttribute(fused_mlp7_kernel,
                         cudaFuncAttributeMaxDynamicSharedMemorySize, SMEM_BYTES);
    fused_mlp7_kernel<<<NBLOCKS, THREADS, SMEM_BYTES>>>(x, w1, w2, w3, w4, w5, w6, w7, out);
}